// round 1
// baseline (speedup 1.0000x reference)
#include <cuda_runtime.h>
#include <math.h>
#include <stdint.h>

// Problem constants (fixed by setup_inputs)
#define N_NODES 32768
#define NB      64
#define LSEQ    512
#define DIM     256
#define HID     512
#define GI3     1536   // 3*HID

// ---------------- scratch (static device globals; no allocation) ----------------
__device__ float g_h0 [(size_t)N_NODES * DIM];   // embedded nodes
__device__ float g_t  [(size_t)N_NODES * HID];   // GEMM output (pre-aggregation)
__device__ float g_acc[(size_t)N_NODES * HID];   // scatter accumulator
__device__ float g_h1 [(size_t)N_NODES * HID];
__device__ float g_h2 [(size_t)N_NODES * HID];
__device__ float g_gi [(size_t)N_NODES * GI3];   // precomputed input-gates for GRU
__device__ int   g_deg [N_NODES];
__device__ float g_dinv[N_NODES];
__device__ float g_hA  [NB * HID];
__device__ float g_hB  [NB * HID];
__device__ float g_hsum[NB * HID];

// ---------------- small kernels ----------------
__global__ void k_count(const int* __restrict__ dst, int* __restrict__ deg, int E) {
    int i = blockIdx.x * 256 + threadIdx.x;
    if (i < E) atomicAdd(&deg[dst[i]], 1);
}

__global__ void k_dinv(const int* __restrict__ deg, float* __restrict__ dinv) {
    int i = blockIdx.x * 256 + threadIdx.x;
    if (i < N_NODES) dinv[i] = rsqrtf((float)(deg[i] + 1));  // +1 self loop
}

__global__ void k_embed(const int* __restrict__ x, const float* __restrict__ emb,
                        float* __restrict__ h0) {
    int n = blockIdx.x;
    int d = threadIdx.x;          // 256 threads
    h0[(size_t)n * DIM + d] = emb[(size_t)x[n] * DIM + d];
}

// GCN edge scatter: acc[dst] += t[src] * dinv[src]*dinv[dst]   (one warp per edge)
__global__ void k_scatter(const float* __restrict__ t, const int* __restrict__ src,
                          const int* __restrict__ dst, const float* __restrict__ dinv,
                          float* __restrict__ acc, int E) {
    int e = blockIdx.x * 8 + (threadIdx.x >> 5);
    if (e >= E) return;
    int lane = threadIdx.x & 31;
    int s = src[e], d = dst[e];
    float c = dinv[s] * dinv[d];
    const float4* tr = (const float4*)(t + (size_t)s * HID);
    float* ar = acc + (size_t)d * HID;
#pragma unroll
    for (int i = 0; i < 4; i++) {
        int j = lane + i * 32;          // 128 float4 per row
        float4 v = tr[j];
        atomicAdd(ar + j * 4 + 0, v.x * c);
        atomicAdd(ar + j * 4 + 1, v.y * c);
        atomicAdd(ar + j * 4 + 2, v.z * c);
        atomicAdd(ar + j * 4 + 3, v.w * c);
    }
}

// out = relu(acc + t*dinv^2 (self loop) + bias)
__global__ void k_finish(const float* __restrict__ acc, const float* __restrict__ t,
                         const float* __restrict__ dinv, const float* __restrict__ bias,
                         float* __restrict__ out) {
    size_t idx = (size_t)blockIdx.x * 256 + threadIdx.x;
    int row = (int)(idx >> 9);
    int col = (int)(idx & 511);
    float di = dinv[row];
    float v = acc[idx] + t[idx] * di * di + bias[col];
    out[idx] = fmaxf(v, 0.0f);
}

// ---------------- tiled SGEMM: C[M,N] = A[M,K] @ (B or B^T) (+bias) ----------------
// BM=64, BN=64, BK=16, 256 threads, 4x4 per thread. All dims exact multiples.
template<bool TRANSB, bool ADD_BIAS>
__global__ void __launch_bounds__(256) sgemm_kernel(
    const float* __restrict__ A, const float* __restrict__ B,
    const float* __restrict__ bias, float* __restrict__ C,
    int M, int N, int K) {
    __shared__ float As[16][64];
    __shared__ float Bs[16][64];
    int tid = threadIdx.x;
    int tx = tid & 15, ty = tid >> 4;
    int row0 = blockIdx.y * 64;
    int col0 = blockIdx.x * 64;
    float acc[4][4] = {};

    int la_m = tid >> 2;            // 0..63
    int la_k = (tid & 3) << 2;      // 0,4,8,12

    for (int kk = 0; kk < K; kk += 16) {
        {   // A tile: [64 rows][16 k] -> As[k][m]
            float4 v = *(const float4*)(A + (size_t)(row0 + la_m) * K + kk + la_k);
            As[la_k + 0][la_m] = v.x; As[la_k + 1][la_m] = v.y;
            As[la_k + 2][la_m] = v.z; As[la_k + 3][la_m] = v.w;
        }
        if (TRANSB) {  // B is [N,K] row-major; Bs[k][n] = B[n][k]
            float4 v = *(const float4*)(B + (size_t)(col0 + la_m) * K + kk + la_k);
            Bs[la_k + 0][la_m] = v.x; Bs[la_k + 1][la_m] = v.y;
            Bs[la_k + 2][la_m] = v.z; Bs[la_k + 3][la_m] = v.w;
        } else {       // B is [K,N] row-major
            int lb_k = tid >> 4;            // 0..15
            int lb_n = (tid & 15) << 2;     // 0..60
            float4 v = *(const float4*)(B + (size_t)(kk + lb_k) * N + col0 + lb_n);
            *(float4*)&Bs[lb_k][lb_n] = v;
        }
        __syncthreads();
#pragma unroll
        for (int k = 0; k < 16; k++) {
            float4 a  = *(const float4*)&As[k][ty << 2];
            float4 bv = *(const float4*)&Bs[k][tx << 2];
            acc[0][0] += a.x * bv.x; acc[0][1] += a.x * bv.y; acc[0][2] += a.x * bv.z; acc[0][3] += a.x * bv.w;
            acc[1][0] += a.y * bv.x; acc[1][1] += a.y * bv.y; acc[1][2] += a.y * bv.z; acc[1][3] += a.y * bv.w;
            acc[2][0] += a.z * bv.x; acc[2][1] += a.z * bv.y; acc[2][2] += a.z * bv.z; acc[2][3] += a.z * bv.w;
            acc[3][0] += a.w * bv.x; acc[3][1] += a.w * bv.y; acc[3][2] += a.w * bv.z; acc[3][3] += a.w * bv.w;
        }
        __syncthreads();
    }
    float4 bb = {0, 0, 0, 0};
    if (ADD_BIAS) bb = *(const float4*)(bias + col0 + (tx << 2));
#pragma unroll
    for (int i = 0; i < 4; i++) {
        float4 o = {acc[i][0] + bb.x, acc[i][1] + bb.y, acc[i][2] + bb.z, acc[i][3] + bb.w};
        *(float4*)(C + (size_t)(row0 + (ty << 2) + i) * N + col0 + (tx << 2)) = o;
    }
}

// ---------------- GRU step (one kernel per timestep, graph-captured) ----------------
// 128 blocks x 256 threads. Block cb owns output columns [cb*4, cb*4+4).
// Full previous h state [64][512] staged in padded smem, plus the 12 Whh rows
// this block needs. Thread (b, c) computes 3 K=512 dot products with LDS128.
#define HPAD 516   // floats per h row in smem (stride 129 float4 -> conflict free)
#define WPAD 520   // floats per W row in smem (stride 130 float4)
#define GRU_SMEM ((64 * HPAD + 12 * WPAD) * 4)

__device__ __forceinline__ float sigmoidf_(float x) { return 1.0f / (1.0f + __expf(-x)); }

__global__ void __launch_bounds__(256) k_gru_step(
    const float* __restrict__ gi, const float* __restrict__ hprev,
    const float* __restrict__ Whh, const float* __restrict__ bhh,
    float* __restrict__ hnext, float* __restrict__ hsum, int tstep) {
    extern __shared__ float smem[];
    float* sh_h = smem;               // [64][HPAD]
    float* sh_w = smem + 64 * HPAD;   // [12][WPAD]
    int tid = threadIdx.x;
    int cb = blockIdx.x;              // 0..127

    // stage h: 64*512 floats = 8192 float4
    const float4* hp4 = (const float4*)hprev;
    float4* shh4 = (float4*)sh_h;
#pragma unroll
    for (int i = 0; i < 32; i++) {
        int idx = tid + i * 256;
        int b = idx >> 7, k4 = idx & 127;
        shh4[b * 129 + k4] = hp4[idx];
    }
    // stage 12 Whh rows (gates r,z,n for 4 cols): 1536 float4
    const float4* w4 = (const float4*)Whh;
    float4* shw4 = (float4*)sh_w;
#pragma unroll
    for (int i = 0; i < 6; i++) {
        int idx = tid + i * 256;
        int r = idx >> 7, k4 = idx & 127;
        int row = (r >> 2) * HID + cb * 4 + (r & 3);
        shw4[r * 130 + k4] = w4[(size_t)row * 128 + k4];
    }
    __syncthreads();

    int c = tid & 3;
    int b = tid >> 2;
    const float4* hr4 = shh4 + b * 129;
    const float4* wr4 = shw4 + (0 + c) * 130;
    const float4* wz4 = shw4 + (4 + c) * 130;
    const float4* wn4 = shw4 + (8 + c) * 130;
    float4 ar = {0,0,0,0}, az = {0,0,0,0}, an = {0,0,0,0};
#pragma unroll 4
    for (int k = 0; k < 128; k++) {
        float4 h = hr4[k];
        float4 wr = wr4[k], wz = wz4[k], wn = wn4[k];
        ar.x += h.x * wr.x; ar.y += h.y * wr.y; ar.z += h.z * wr.z; ar.w += h.w * wr.w;
        az.x += h.x * wz.x; az.y += h.y * wz.y; az.z += h.z * wz.z; az.w += h.w * wz.w;
        an.x += h.x * wn.x; an.y += h.y * wn.y; an.z += h.z * wn.z; an.w += h.w * wn.w;
    }
    float accr = (ar.x + ar.y) + (ar.z + ar.w);
    float accz = (az.x + az.y) + (az.z + az.w);
    float accn = (an.x + an.y) + (an.z + an.w);

    int col = cb * 4 + c;
    size_t nrow = (size_t)b * LSEQ + tstep;   // node index for (graph b, step t)
    const float* girow = gi + nrow * GI3;
    float rr = sigmoidf_(girow[col]        + accr + bhh[col]);
    float zz = sigmoidf_(girow[HID + col]  + accz + bhh[HID + col]);
    float nn = tanhf(girow[2*HID + col] + rr * (accn + bhh[2*HID + col]));
    float hold = sh_h[b * HPAD + col];
    float hnew = (1.0f - zz) * nn + zz * hold;
    hnext[b * HID + col] = hnew;
    hsum [b * HID + col] += hnew;
}

// ---------------- head: mean -> fc1(relu) -> fc2(sigmoid) ----------------
__global__ void __launch_bounds__(512) k_head(
    const float* __restrict__ hsum, const float* __restrict__ focal,
    const float* __restrict__ fc1w, const float* __restrict__ fc1b,
    const float* __restrict__ fc2w, const float* __restrict__ fc2b,
    float* __restrict__ out) {
    __shared__ float g[HID + 1];
    __shared__ float red[HID];
    int b = blockIdx.x, j = threadIdx.x;
    g[j] = hsum[b * HID + j] * (1.0f / (float)LSEQ);
    if (j == 0) g[HID] = focal[b];
    __syncthreads();
    float acc = fc1b[j];
    for (int k = 0; k < HID + 1; k++) acc += g[k] * fc1w[(size_t)k * HID + j];
    float a = fmaxf(acc, 0.0f);
    red[j] = a * fc2w[j];
    __syncthreads();
    for (int s = 256; s > 0; s >>= 1) {
        if (j < s) red[j] += red[j + s];
        __syncthreads();
    }
    if (j == 0) out[b] = sigmoidf_(red[0] + fc2b[0]);
}

// ---------------- launch ----------------
extern "C" void kernel_launch(void* const* d_in, const int* in_sizes, int n_in,
                              void* d_out, int out_size) {
    const int*   x     = (const int*)  d_in[0];
    const int*   edge  = (const int*)  d_in[1];
    // d_in[2] = batch_idx (arange(N)//L -> identity reshape, unused)
    const float* focal = (const float*)d_in[3];
    const float* emb   = (const float*)d_in[4];
    const float* W1    = (const float*)d_in[5];
    const float* b1    = (const float*)d_in[6];
    const float* W2    = (const float*)d_in[7];
    const float* b2    = (const float*)d_in[8];
    const float* Wih   = (const float*)d_in[9];
    const float* Whh   = (const float*)d_in[10];
    const float* bih   = (const float*)d_in[11];
    const float* bhh   = (const float*)d_in[12];
    const float* fc1w  = (const float*)d_in[13];
    const float* fc1b  = (const float*)d_in[14];
    const float* fc2w  = (const float*)d_in[15];
    const float* fc2b  = (const float*)d_in[16];
    int E = in_sizes[1] / 2;
    const int* src = edge;
    const int* dst = edge + E;

    float *h0, *t, *acc, *h1, *h2, *gi, *dinv, *hA, *hB, *hsum;
    int* deg;
    cudaGetSymbolAddress((void**)&h0,   g_h0);
    cudaGetSymbolAddress((void**)&t,    g_t);
    cudaGetSymbolAddress((void**)&acc,  g_acc);
    cudaGetSymbolAddress((void**)&h1,   g_h1);
    cudaGetSymbolAddress((void**)&h2,   g_h2);
    cudaGetSymbolAddress((void**)&gi,   g_gi);
    cudaGetSymbolAddress((void**)&deg,  g_deg);
    cudaGetSymbolAddress((void**)&dinv, g_dinv);
    cudaGetSymbolAddress((void**)&hA,   g_hA);
    cudaGetSymbolAddress((void**)&hB,   g_hB);
    cudaGetSymbolAddress((void**)&hsum, g_hsum);

    cudaFuncSetAttribute(k_gru_step, cudaFuncAttributeMaxDynamicSharedMemorySize, GRU_SMEM);

    // degree / normalization (shared by both GCN layers)
    cudaMemsetAsync(deg, 0, N_NODES * sizeof(int), 0);
    k_count<<<(E + 255) / 256, 256>>>(dst, deg, E);
    k_dinv<<<N_NODES / 256, 256>>>(deg, dinv);

    // GCN layer 1
    k_embed<<<N_NODES, 256>>>(x, emb, h0);
    sgemm_kernel<false, false><<<dim3(HID / 64, N_NODES / 64), 256>>>(h0, W1, nullptr, t, N_NODES, HID, DIM);
    cudaMemsetAsync(acc, 0, (size_t)N_NODES * HID * sizeof(float), 0);
    k_scatter<<<(E + 7) / 8, 256>>>(t, src, dst, dinv, acc, E);
    k_finish<<<(int)((size_t)N_NODES * HID / 256), 256>>>(acc, t, dinv, b1, h1);

    // GCN layer 2
    sgemm_kernel<false, false><<<dim3(HID / 64, N_NODES / 64), 256>>>(h1, W2, nullptr, t, N_NODES, HID, HID);
    cudaMemsetAsync(acc, 0, (size_t)N_NODES * HID * sizeof(float), 0);
    k_scatter<<<(E + 7) / 8, 256>>>(t, src, dst, dinv, acc, E);
    k_finish<<<(int)((size_t)N_NODES * HID / 256), 256>>>(acc, t, dinv, b2, h2);

    // GRU input gates for all timesteps at once: gi = h2 @ Wih^T + bih
    sgemm_kernel<true, true><<<dim3(GI3 / 64, N_NODES / 64), 256>>>(h2, Wih, bih, gi, N_NODES, GI3, HID);

    // sequential GRU
    cudaMemsetAsync(hA,   0, NB * HID * sizeof(float), 0);
    cudaMemsetAsync(hsum, 0, NB * HID * sizeof(float), 0);
    for (int ts = 0; ts < LSEQ; ts++) {
        const float* hc = (ts & 1) ? hB : hA;
        float*       hn = (ts & 1) ? hA : hB;
        k_gru_step<<<128, 256, GRU_SMEM>>>(gi, hc, Whh, bhh, hn, hsum, ts);
    }

    // head
    k_head<<<NB, 512>>>(hsum, focal, fc1w, fc1b, fc2w, fc2b, (float*)d_out);
}

// round 2
// speedup vs baseline: 2.0182x; 2.0182x over previous
#include <cuda_runtime.h>
#include <math.h>
#include <stdint.h>

// Problem constants (fixed by setup_inputs)
#define N_NODES 32768
#define NB      64
#define LSEQ    512
#define DIM     256
#define HID     512
#define GI3     1536   // 3*HID
#define EDGES   524288
#define NBLK_GRU 128

// ---------------- scratch (static device globals; no allocation) ----------------
__device__ float g_h0 [(size_t)N_NODES * DIM];
__device__ float g_t  [(size_t)N_NODES * HID];
__device__ float g_h1 [(size_t)N_NODES * HID];
__device__ float g_h2 [(size_t)N_NODES * HID];
__device__ float g_gi [(size_t)N_NODES * GI3];
__device__ float g_gi2[(size_t)LSEQ * GI3 * NB];   // [t][gatecol][b]
__device__ int   g_deg [N_NODES];
__device__ float g_dinv[N_NODES];
__device__ int   g_off [N_NODES + 1];
__device__ int   g_cursor[N_NODES];
__device__ int   g_csrc[EDGES];
__device__ float g_ccoef[EDGES];
__device__ float g_hbuf[2][NB * HID];
__device__ float g_hsum[NB * HID];
__device__ int   g_bar;

// ---------------- degree / CSR build ----------------
__global__ void k_count(const int* __restrict__ dst, int* __restrict__ deg, int E) {
    int i = blockIdx.x * 256 + threadIdx.x;
    if (i < E) atomicAdd(&deg[dst[i]], 1);
}

__global__ void k_dinv(const int* __restrict__ deg, float* __restrict__ dinv) {
    int i = blockIdx.x * 256 + threadIdx.x;
    if (i < N_NODES) dinv[i] = rsqrtf((float)(deg[i] + 1));  // +1 self loop
}

// exclusive scan of deg -> off (N+1 entries), zero cursor. 1 block x 1024 thr.
__global__ void __launch_bounds__(1024) k_scan(const int* __restrict__ deg,
                                               int* __restrict__ off,
                                               int* __restrict__ cursor) {
    __shared__ int ssum[1024];
    int tid = threadIdx.x;
    int base = tid * 32;
    int loc[32];
    int s = 0;
#pragma unroll
    for (int i = 0; i < 32; i++) { loc[i] = s; s += deg[base + i]; }
    ssum[tid] = s;
    __syncthreads();
    for (int ofs = 1; ofs < 1024; ofs <<= 1) {
        int v = (tid >= ofs) ? ssum[tid - ofs] : 0;
        __syncthreads();
        ssum[tid] += v;
        __syncthreads();
    }
    int pre = (tid == 0) ? 0 : ssum[tid - 1];
#pragma unroll
    for (int i = 0; i < 32; i++) { off[base + i] = pre + loc[i]; cursor[base + i] = 0; }
    if (tid == 1023) off[N_NODES] = ssum[1023];
}

__global__ void k_fill(const int* __restrict__ src, const int* __restrict__ dst,
                       const float* __restrict__ dinv, const int* __restrict__ off,
                       int* __restrict__ cursor, int* __restrict__ csrc,
                       float* __restrict__ ccoef, int E) {
    int e = blockIdx.x * 256 + threadIdx.x;
    if (e >= E) return;
    int s = src[e], d = dst[e];
    int p = atomicAdd(&cursor[d], 1);
    int slot = off[d] + p;
    csrc[slot] = s;
    ccoef[slot] = dinv[s] * dinv[d];
}

__global__ void k_embed(const int* __restrict__ x, const float* __restrict__ emb,
                        float* __restrict__ h0) {
    int n = blockIdx.x;
    int d = threadIdx.x;          // 256 threads
    h0[(size_t)n * DIM + d] = emb[(size_t)x[n] * DIM + d];
}

// ---------------- CSR gather: out = relu( sum_in t[src]*coef + t[n]*dinv^2 + bias )
// block 256 = 8 warps = 2 nodes x 4 col-chunks; warp handles 128 cols (float4/lane)
__global__ void __launch_bounds__(256) k_gather(
    const float* __restrict__ t, const int* __restrict__ csrc,
    const float* __restrict__ ccoef, const int* __restrict__ off,
    const float* __restrict__ dinv, const float* __restrict__ bias,
    float* __restrict__ out) {
    int w = threadIdx.x >> 5, lane = threadIdx.x & 31;
    int n = blockIdx.x * 2 + (w >> 2);
    int chunk = w & 3;
    int c4 = chunk * 32 + lane;   // float4 column index 0..127
    float di = dinv[n];
    float sc = di * di;
    float4 v = ((const float4*)(t + (size_t)n * HID))[c4];
    float4 acc = {v.x * sc, v.y * sc, v.z * sc, v.w * sc};
    int j0 = off[n], j1 = off[n + 1];
#pragma unroll 2
    for (int j = j0; j < j1; j++) {
        int s = __ldg(&csrc[j]);
        float cf = __ldg(&ccoef[j]);
        float4 u = ((const float4*)(t + (size_t)s * HID))[c4];
        acc.x += u.x * cf; acc.y += u.y * cf; acc.z += u.z * cf; acc.w += u.w * cf;
    }
    float4 bb = ((const float4*)bias)[c4];
    float4 o = {fmaxf(acc.x + bb.x, 0.f), fmaxf(acc.y + bb.y, 0.f),
                fmaxf(acc.z + bb.z, 0.f), fmaxf(acc.w + bb.w, 0.f)};
    ((float4*)(out + (size_t)n * HID))[c4] = o;
}

// ---------------- tiled SGEMM: C[M,N] = A[M,K] @ (B or B^T) (+bias) ----------------
template<bool TRANSB, bool ADD_BIAS>
__global__ void __launch_bounds__(256) sgemm_kernel(
    const float* __restrict__ A, const float* __restrict__ B,
    const float* __restrict__ bias, float* __restrict__ C,
    int M, int N, int K) {
    __shared__ float As[16][64];
    __shared__ float Bs[16][64];
    int tid = threadIdx.x;
    int tx = tid & 15, ty = tid >> 4;
    int row0 = blockIdx.y * 64;
    int col0 = blockIdx.x * 64;
    float acc[4][4] = {};
    int la_m = tid >> 2;
    int la_k = (tid & 3) << 2;
    for (int kk = 0; kk < K; kk += 16) {
        {
            float4 v = *(const float4*)(A + (size_t)(row0 + la_m) * K + kk + la_k);
            As[la_k + 0][la_m] = v.x; As[la_k + 1][la_m] = v.y;
            As[la_k + 2][la_m] = v.z; As[la_k + 3][la_m] = v.w;
        }
        if (TRANSB) {
            float4 v = *(const float4*)(B + (size_t)(col0 + la_m) * K + kk + la_k);
            Bs[la_k + 0][la_m] = v.x; Bs[la_k + 1][la_m] = v.y;
            Bs[la_k + 2][la_m] = v.z; Bs[la_k + 3][la_m] = v.w;
        } else {
            int lb_k = tid >> 4;
            int lb_n = (tid & 15) << 2;
            float4 v = *(const float4*)(B + (size_t)(kk + lb_k) * N + col0 + lb_n);
            *(float4*)&Bs[lb_k][lb_n] = v;
        }
        __syncthreads();
#pragma unroll
        for (int k = 0; k < 16; k++) {
            float4 a  = *(const float4*)&As[k][ty << 2];
            float4 bv = *(const float4*)&Bs[k][tx << 2];
            acc[0][0] += a.x * bv.x; acc[0][1] += a.x * bv.y; acc[0][2] += a.x * bv.z; acc[0][3] += a.x * bv.w;
            acc[1][0] += a.y * bv.x; acc[1][1] += a.y * bv.y; acc[1][2] += a.y * bv.z; acc[1][3] += a.y * bv.w;
            acc[2][0] += a.z * bv.x; acc[2][1] += a.z * bv.y; acc[2][2] += a.z * bv.z; acc[2][3] += a.z * bv.w;
            acc[3][0] += a.w * bv.x; acc[3][1] += a.w * bv.y; acc[3][2] += a.w * bv.z; acc[3][3] += a.w * bv.w;
        }
        __syncthreads();
    }
    float4 bb = {0, 0, 0, 0};
    if (ADD_BIAS) bb = *(const float4*)(bias + col0 + (tx << 2));
#pragma unroll
    for (int i = 0; i < 4; i++) {
        float4 o = {acc[i][0] + bb.x, acc[i][1] + bb.y, acc[i][2] + bb.z, acc[i][3] + bb.w};
        *(float4*)(C + (size_t)(row0 + (ty << 2) + i) * N + col0 + (tx << 2)) = o;
    }
}

// ---------------- gi transpose: gi[b*512+t][j] -> gi2[t][j][b] ----------------
__global__ void __launch_bounds__(256) k_tr(const float* __restrict__ gi,
                                            float* __restrict__ gi2) {
    __shared__ float s[64][132];
    int tid = threadIdx.x;
    int t = blockIdx.x;
    int j0 = blockIdx.y * 128;
#pragma unroll
    for (int i = 0; i < 8; i++) {
        int idx = tid + i * 256;
        int b = idx >> 5, c4 = idx & 31;
        float4 v = ((const float4*)(gi + (size_t)(b * LSEQ + t) * GI3 + j0))[c4];
        *(float4*)&s[b][c4 * 4] = v;
    }
    __syncthreads();
    size_t obase = (size_t)t * (GI3 * NB);
#pragma unroll
    for (int i = 0; i < 32; i++) {
        int idx = tid + i * 256;
        int j = idx >> 6, b = idx & 63;
        gi2[obase + (size_t)(j0 + j) * NB + b] = s[b][j];
    }
}

// ---------------- persistent GRU ----------------
// 128 blocks x 256 threads, one block per 4 h-columns. Single launch, gmem
// spin barrier per step, double-buffered h in gmem, Whh resident in smem.
// smem: hs 64x128 float4 (XOR-swizzled), ws 12x130 float4, red 256x26 floats.
#define HS_F4   8192
#define WS_F4   (12 * 130)
#define RED_F   (256 * 26)
#define GRU_SMEM ((HS_F4 + WS_F4) * 16 + RED_F * 4)

__device__ __forceinline__ float sigmoidf_(float x) { return 1.0f / (1.0f + __expf(-x)); }

__global__ void __launch_bounds__(256, 1) k_gru_all(
    const float* __restrict__ gi2, const float* __restrict__ Whh,
    const float* __restrict__ bhh, float* __restrict__ hsum,
    float* __restrict__ hbuf0, float* __restrict__ hbuf1, int* bar) {
    extern __shared__ float sm[];
    float4* hs4 = (float4*)sm;
    float4* ws4 = hs4 + HS_F4;
    float*  red = sm + (HS_F4 + WS_F4) * 4;
    int tid = threadIdx.x;
    int bk = blockIdx.x;
    int col0 = bk * 4;

    // load Whh slice once: rows (gate*HID + col0 + c) for gate 0..2, c 0..3
#pragma unroll
    for (int i = 0; i < 6; i++) {
        int idx = tid + i * 256;
        int r = idx >> 7, k4 = idx & 127;
        int wrow = (r >> 2) * HID + col0 + (r & 3);
        ws4[r * 130 + k4] = __ldg((const float4*)Whh + (size_t)wrow * 128 + k4);
    }

    // gate-phase identity
    int gb = tid >> 2, gc = tid & 3;
    int col = col0 + gc;
    float bh_r = bhh[col], bh_z = bhh[HID + col], bh_n = bhh[2 * HID + col];
    int wkp = ((gc >> 1) << 4) + (gb >> 2);
    int iip = ((gc & 1) << 2) + (gb & 3);
    int hxor = bk ^ ((gb >> 2) & 7);
    float hsum_acc = 0.0f;

    // worker identity (design B: 4 graphs x 2 cols x 3 gates, 8 k-groups)
    int wk = tid & 31, kg = tid >> 5;
    int c2 = wk >> 4, bq = wk & 15;
    int xorb = bq & 7;
    int b0 = bq * 4;
    int kbase = kg * 16;
    const float4* hp0 = hs4 + (size_t)(b0 + 0) * 128;
    const float4* hp1 = hs4 + (size_t)(b0 + 1) * 128;
    const float4* hp2 = hs4 + (size_t)(b0 + 2) * 128;
    const float4* hp3 = hs4 + (size_t)(b0 + 3) * 128;
    const float4* wp0 = ws4 + (0 * 4 + c2 * 2) * 130;   // gate r, cols cc=0,1
    const float4* wp1 = ws4 + (1 * 4 + c2 * 2) * 130;   // gate z
    const float4* wp2 = ws4 + (2 * 4 + c2 * 2) * 130;   // gate n

    __syncthreads();

    for (int t = 0; t < LSEQ; t++) {
        const float* hb = (t & 1) ? hbuf1 : hbuf0;
        float*       hn = (t & 1) ? hbuf0 : hbuf1;

        // prefetch gate inputs for this step (hidden under staging+compute)
        size_t gbase = (size_t)t * (GI3 * NB) + (size_t)col * NB + gb;
        float gir = __ldcg(gi2 + gbase);
        float giz = __ldcg(gi2 + gbase + (size_t)HID * NB);
        float gin = __ldcg(gi2 + gbase + (size_t)(2 * HID) * NB);

        // stage h (bypass L1 - other SMs wrote it)
#pragma unroll
        for (int i = 0; i < 32; i++) {
            int idx = tid + i * 256;
            int b = idx >> 7, k4 = idx & 127;
            float4 v = __ldcg((const float4*)hb + idx);
            hs4[b * 128 + (k4 ^ ((b >> 2) & 7))] = v;
        }
        __syncthreads();

        // partial dots over this k-group
        float acc[3][2][4] = {};
#pragma unroll
        for (int kk = 0; kk < 16; kk++) {
            int k4 = kbase + kk;
            int hk = k4 ^ xorb;
            float4 h0 = hp0[hk], h1 = hp1[hk], h2 = hp2[hk], h3 = hp3[hk];
#pragma unroll
            for (int cc = 0; cc < 2; cc++) {
                float4 wr = wp0[cc * 130 + k4];
                float4 wz = wp1[cc * 130 + k4];
                float4 wn = wp2[cc * 130 + k4];
                acc[0][cc][0] += h0.x*wr.x + h0.y*wr.y + h0.z*wr.z + h0.w*wr.w;
                acc[0][cc][1] += h1.x*wr.x + h1.y*wr.y + h1.z*wr.z + h1.w*wr.w;
                acc[0][cc][2] += h2.x*wr.x + h2.y*wr.y + h2.z*wr.z + h2.w*wr.w;
                acc[0][cc][3] += h3.x*wr.x + h3.y*wr.y + h3.z*wr.z + h3.w*wr.w;
                acc[1][cc][0] += h0.x*wz.x + h0.y*wz.y + h0.z*wz.z + h0.w*wz.w;
                acc[1][cc][1] += h1.x*wz.x + h1.y*wz.y + h1.z*wz.z + h1.w*wz.w;
                acc[1][cc][2] += h2.x*wz.x + h2.y*wz.y + h2.z*wz.z + h2.w*wz.w;
                acc[1][cc][3] += h3.x*wz.x + h3.y*wz.y + h3.z*wz.z + h3.w*wz.w;
                acc[2][cc][0] += h0.x*wn.x + h0.y*wn.y + h0.z*wn.z + h0.w*wn.w;
                acc[2][cc][1] += h1.x*wn.x + h1.y*wn.y + h1.z*wn.z + h1.w*wn.w;
                acc[2][cc][2] += h2.x*wn.x + h2.y*wn.y + h2.z*wn.z + h2.w*wn.w;
                acc[2][cc][3] += h3.x*wn.x + h3.y*wn.y + h3.z*wn.z + h3.w*wn.w;
            }
        }
        {
            float* rp = red + (kg * 32 + wk) * 26;
#pragma unroll
            for (int g = 0; g < 3; g++)
#pragma unroll
                for (int cc = 0; cc < 2; cc++)
#pragma unroll
                    for (int i = 0; i < 4; i++)
                        rp[g * 8 + cc * 4 + i] = acc[g][cc][i];
        }
        __syncthreads();

        // reduce across 8 k-groups + gates + state update
        float s0 = 0, s1 = 0, s2 = 0;
#pragma unroll
        for (int q = 0; q < 8; q++) {
            const float* rp = red + (q * 32 + wkp) * 26 + iip;
            s0 += rp[0]; s1 += rp[8]; s2 += rp[16];
        }
        float r  = sigmoidf_(gir + s0 + bh_r);
        float z  = sigmoidf_(giz + s1 + bh_z);
        float nn = tanhf(gin + r * (s2 + bh_n));
        float hold = ((const float*)(hs4 + (size_t)gb * 128 + hxor))[gc];
        float hnew = (1.0f - z) * nn + z * hold;
        __stcg(hn + gb * HID + col, hnew);
        hsum_acc += hnew;

        // chip-wide barrier
        __threadfence();
        __syncthreads();
        if (tid == 0) {
            atomicAdd(bar, 1);
            int target = NBLK_GRU * (t + 1);
            while (*((volatile int*)bar) < target) { }
        }
        __syncthreads();
    }
    hsum[gb * HID + col] = hsum_acc;
}

// ---------------- head ----------------
__global__ void __launch_bounds__(512) k_head(
    const float* __restrict__ hsum, const float* __restrict__ focal,
    const float* __restrict__ fc1w, const float* __restrict__ fc1b,
    const float* __restrict__ fc2w, const float* __restrict__ fc2b,
    float* __restrict__ out) {
    __shared__ float g[HID + 1];
    __shared__ float red[HID];
    int b = blockIdx.x, j = threadIdx.x;
    g[j] = hsum[b * HID + j] * (1.0f / (float)LSEQ);
    if (j == 0) g[HID] = focal[b];
    __syncthreads();
    float acc = fc1b[j];
    for (int k = 0; k < HID + 1; k++) acc += g[k] * fc1w[(size_t)k * HID + j];
    float a = fmaxf(acc, 0.0f);
    red[j] = a * fc2w[j];
    __syncthreads();
    for (int s = 256; s > 0; s >>= 1) {
        if (j < s) red[j] += red[j + s];
        __syncthreads();
    }
    if (j == 0) out[b] = sigmoidf_(red[0] + fc2b[0]);
}

// ---------------- launch ----------------
extern "C" void kernel_launch(void* const* d_in, const int* in_sizes, int n_in,
                              void* d_out, int out_size) {
    const int*   x     = (const int*)  d_in[0];
    const int*   edge  = (const int*)  d_in[1];
    const float* focal = (const float*)d_in[3];
    const float* emb   = (const float*)d_in[4];
    const float* W1    = (const float*)d_in[5];
    const float* b1    = (const float*)d_in[6];
    const float* W2    = (const float*)d_in[7];
    const float* b2    = (const float*)d_in[8];
    const float* Wih   = (const float*)d_in[9];
    const float* Whh   = (const float*)d_in[10];
    const float* bih   = (const float*)d_in[11];
    const float* bhh   = (const float*)d_in[12];
    const float* fc1w  = (const float*)d_in[13];
    const float* fc1b  = (const float*)d_in[14];
    const float* fc2w  = (const float*)d_in[15];
    const float* fc2b  = (const float*)d_in[16];
    int E = in_sizes[1] / 2;
    const int* src = edge;
    const int* dst = edge + E;

    float *h0, *t, *h1, *h2, *gi, *gi2, *dinv, *hbuf, *hsum, *ccoef;
    int *deg, *off, *cursor, *csrc, *bar;
    cudaGetSymbolAddress((void**)&h0,    g_h0);
    cudaGetSymbolAddress((void**)&t,     g_t);
    cudaGetSymbolAddress((void**)&h1,    g_h1);
    cudaGetSymbolAddress((void**)&h2,    g_h2);
    cudaGetSymbolAddress((void**)&gi,    g_gi);
    cudaGetSymbolAddress((void**)&gi2,   g_gi2);
    cudaGetSymbolAddress((void**)&deg,   g_deg);
    cudaGetSymbolAddress((void**)&dinv,  g_dinv);
    cudaGetSymbolAddress((void**)&off,   g_off);
    cudaGetSymbolAddress((void**)&cursor,g_cursor);
    cudaGetSymbolAddress((void**)&csrc,  g_csrc);
    cudaGetSymbolAddress((void**)&ccoef, g_ccoef);
    cudaGetSymbolAddress((void**)&hbuf,  g_hbuf);
    cudaGetSymbolAddress((void**)&hsum,  g_hsum);
    cudaGetSymbolAddress((void**)&bar,   g_bar);

    cudaFuncSetAttribute(k_gru_all, cudaFuncAttributeMaxDynamicSharedMemorySize, GRU_SMEM);

    // CSR build (graph fixed for both layers)
    cudaMemsetAsync(deg, 0, N_NODES * sizeof(int), 0);
    k_count<<<(E + 255) / 256, 256>>>(dst, deg, E);
    k_dinv<<<N_NODES / 256, 256>>>(deg, dinv);
    k_scan<<<1, 1024>>>(deg, off, cursor);
    k_fill<<<(E + 255) / 256, 256>>>(src, dst, dinv, off, cursor, csrc, ccoef, E);

    // GCN layer 1
    k_embed<<<N_NODES, 256>>>(x, emb, h0);
    sgemm_kernel<false, false><<<dim3(HID / 64, N_NODES / 64), 256>>>(h0, W1, nullptr, t, N_NODES, HID, DIM);
    k_gather<<<N_NODES / 2, 256>>>(t, csrc, ccoef, off, dinv, b1, h1);

    // GCN layer 2
    sgemm_kernel<false, false><<<dim3(HID / 64, N_NODES / 64), 256>>>(h1, W2, nullptr, t, N_NODES, HID, HID);
    k_gather<<<N_NODES / 2, 256>>>(t, csrc, ccoef, off, dinv, b2, h2);

    // GRU input gates for all timesteps: gi = h2 @ Wih^T + bih, then transpose
    sgemm_kernel<true, true><<<dim3(GI3 / 64, N_NODES / 64), 256>>>(h2, Wih, bih, gi, N_NODES, GI3, HID);
    k_tr<<<dim3(LSEQ, GI3 / 128), 256>>>(gi, gi2);

    // persistent GRU
    cudaMemsetAsync(hbuf, 0, NB * HID * sizeof(float), 0);   // hbuf[0] = h_0 = 0
    cudaMemsetAsync(bar, 0, sizeof(int), 0);
    k_gru_all<<<NBLK_GRU, 256, GRU_SMEM>>>(gi2, Whh, bhh, hsum, hbuf, hbuf + NB * HID, bar);

    // head
    k_head<<<NB, 512>>>(hsum, focal, fc1w, fc1b, fc2w, fc2b, (float*)d_out);
}